// round 16
// baseline (speedup 1.0000x reference)
#include <cuda_runtime.h>
#include <stdint.h>

// ---------------------------------------------------------------------------
// KMaxPool: per row of 4096 fp32, top-8 values in original index order.
// One warp per row, single pass (R10 skeleton, best so far).
//   - warp top-8 DISTRIBUTED in lanes 0..7 (val desc), vmin = lane7 val
//   - quad gate: one ballot per 4 elements
//   - HIT PATH (new): argmax-first. Each lane submits only its quad max
//     (one pruned pop loop, winner index shuffled). Then the quad second-max
//     is balloted; only on that rare double-hit is the full 4-element scan
//     run, with the already-inserted max masked to -inf (no duplicates).
//   - pop order need not be index-ascending: order only matters for equal
//     values, and equal values produce identical output bytes either way.
//   - epilogue: rank lanes 0..7 by original index, scatter-store 8 floats
// ---------------------------------------------------------------------------

#define FULLMASK 0xffffffffu
#define NEG_INF  __int_as_float(0xff800000)

// Pop loop: every lane offers candidate (cv, ci). Qualifying lanes are popped
// (ballot order), each insert is a distributed shfl shift of the top-8 list;
// vmin refreshed and mask re-pruned after every insert.
static __device__ __forceinline__ void procpop(float cv, uint32_t ci,
                                               float& val, uint32_t& idx,
                                               float& vmin, bool lane0) {
    unsigned m = __ballot_sync(FULLMASK, cv > vmin);
    while (m) {
        const int L = __ffs(m) - 1;
        m &= m - 1;
        const float    bv = __shfl_sync(FULLMASK, cv, L);
        const uint32_t bi = __shfl_sync(FULLMASK, ci, L);

        const float    pv = __shfl_up_sync(FULLMASK, val, 1);
        const uint32_t pi = __shfl_up_sync(FULLMASK, idx, 1);
        const bool keep = (val >= bv);            // incumbent wins ties
        const bool pk   = lane0 || (pv >= bv);    // lane0: conceptual prev=+inf
        val = keep ? val : (pk ? bv : pv);
        idx = keep ? idx : (pk ? bi : pi);

        vmin = __shfl_sync(FULLMASK, val, 7);
        if (!m) break;
        m &= __ballot_sync(FULLMASK, cv > vmin);  // prune with tighter vmin
    }
}

// Quad: gate ballot, then argmax-first hit processing.
static __device__ __forceinline__ void quad(uint4 q, uint32_t ubase,
                                            float& val, uint32_t& idx,
                                            float& vmin, bool lane0,
                                            int lane) {
    const float vx = __uint_as_float(q.x);
    const float vy = __uint_as_float(q.y);
    const float vz = __uint_as_float(q.z);
    const float vw = __uint_as_float(q.w);
    const float m01 = fmaxf(vx, vy);
    const float m23 = fmaxf(vz, vw);
    const float qm  = fmaxf(m01, m23);

    if (__ballot_sync(FULLMASK, qm > vmin)) {
        const uint32_t lbase = ubase + ((uint32_t)lane << 2);

        // argmax component of this lane's quad
        const bool inhi = (qm != m01);
        const uint32_t ci = inhi ? ((qm == vz) ? 2u : 3u)
                                 : ((qm == vx) ? 0u : 1u);

        // phase 1: insert quad maxes only (one pop loop)
        procpop(qm, lbase + ci, val, idx, vmin, lane0);

        // phase 2: second-max of the quad vs updated vmin (rare)
        const float pmin   = inhi ? fminf(vz, vw) : fminf(vx, vy);
        const float second = fmaxf(inhi ? m01 : m23, pmin);
        if (__ballot_sync(FULLMASK, second > vmin)) {
            // full scan with the inserted max masked out (no duplicates)
            const float wx = (ci == 0u) ? NEG_INF : vx;
            const float wy = (ci == 1u) ? NEG_INF : vy;
            const float wz = (ci == 2u) ? NEG_INF : vz;
            const float ww = (ci == 3u) ? NEG_INF : vw;
            procpop(wx, lbase + 0u, val, idx, vmin, lane0);
            procpop(wy, lbase + 1u, val, idx, vmin, lane0);
            procpop(wz, lbase + 2u, val, idx, vmin, lane0);
            procpop(ww, lbase + 3u, val, idx, vmin, lane0);
        }
    }
}

__global__ void __launch_bounds__(256, 8) kmax8_kernel(const float* __restrict__ x,
                                                       float* __restrict__ out,
                                                       int nrows) {
    const int gw   = (int)((blockIdx.x * blockDim.x + threadIdx.x) >> 5);
    const int lane = threadIdx.x & 31;
    if (gw >= nrows) return;

    const uint4* row = reinterpret_cast<const uint4*>(x) + (size_t)gw * 1024;

    float    val  = NEG_INF;                     // lanes 0..7 = top-8 (desc)
    uint32_t idx  = 0;
    float    vmin = NEG_INF;
    const bool lane0 = (lane == 0);

    // 8 batches x (4 float4 loads = 16 elements) per lane.
#pragma unroll 1
    for (int it = 0; it < 8; ++it) {
        const int p0 = it * 128 + lane;
        uint4 a = row[p0];
        uint4 b = row[p0 + 32];
        uint4 c = row[p0 + 64];
        uint4 d = row[p0 + 96];

        const uint32_t u0 = (uint32_t)(it * 512);
        quad(a, u0 + 0,   val, idx, vmin, lane0, lane);
        quad(b, u0 + 128, val, idx, vmin, lane0, lane);
        quad(c, u0 + 256, val, idx, vmin, lane0, lane);
        quad(d, u0 + 384, val, idx, vmin, lane0, lane);
    }

    // Epilogue: lanes 0..7 hold the top-8 (val desc, unique idx).
    // rank = number of held indices smaller than mine -> output position.
    int rank = 0;
#pragma unroll
    for (int dd = 1; dd < 8; ++dd) {
        uint32_t oi = __shfl_sync(FULLMASK, idx, (lane + dd) & 7);
        rank += (oi < idx) ? 1 : 0;
    }
    if (lane < 8) out[(size_t)gw * 8 + rank] = val;
}

extern "C" void kernel_launch(void* const* d_in, const int* in_sizes, int n_in,
                              void* d_out, int out_size) {
    const float* x = (const float*)d_in[0];
    float* out = (float*)d_out;
    int nrows = in_sizes[0] / 4096;
    const int threads = 256;
    const int warps_per_block = threads / 32;
    int blocks = (nrows + warps_per_block - 1) / warps_per_block;
    kmax8_kernel<<<blocks, threads>>>(x, out, nrows);
}

// round 17
// speedup vs baseline: 1.1201x; 1.1201x over previous
#include <cuda_runtime.h>
#include <stdint.h>

// ---------------------------------------------------------------------------
// KMaxPool: per row of 4096 fp32, top-8 values in original index order.
// One warp per row, single pass. Selection body identical to R10 (best).
// NEW: cp.async (LDGSTS) per-warp DOUBLE-BUFFERED prefetch into smem.
//   - next iteration's 2KB/warp is always in flight while the current
//     iteration is gated/inserted from smem (LDS, 29cy) -> continuous MLP=4
//     instead of burst-then-idle (R10's ~577cy dead wait per iteration)
//   - zero load-destination registers live across compute (R7 failed on this)
//   - per-warp buffers: no __syncthreads, ordering via cp.async.wait_group
//   - 32KB smem/block -> 7 blocks/SM (56 warps); regs ~30
// ---------------------------------------------------------------------------

#define FULLMASK 0xffffffffu

static __device__ __forceinline__ void cpa16(void* dst, const void* src) {
    uint32_t s = (uint32_t)__cvta_generic_to_shared(dst);
    asm volatile("cp.async.cg.shared.global [%0], [%1], 16;" :: "r"(s), "l"(src));
}
#define CPA_COMMIT()  asm volatile("cp.async.commit_group;")
#define CPA_WAIT(N)   asm volatile("cp.async.wait_group %0;" :: "n"(N))

// Exact per-element processing (uniform ballot loop + distributed insert).
static __device__ __forceinline__ void proc(float v, uint32_t ubase,
                                            float& val, uint32_t& idx,
                                            float& vmin, bool lane0) {
    unsigned m = __ballot_sync(FULLMASK, v > vmin);
    while (m) {
        const int L = __ffs(m) - 1;
        m &= m - 1;
        const float    bv = __shfl_sync(FULLMASK, v, L);
        const uint32_t bi = ubase + ((uint32_t)L << 2);

        const float    pv = __shfl_up_sync(FULLMASK, val, 1);
        const uint32_t pi = __shfl_up_sync(FULLMASK, idx, 1);
        const bool keep = (val >= bv);            // incumbent wins ties
        const bool pk   = lane0 || (pv >= bv);    // lane0: conceptual prev=+inf
        val = keep ? val : (pk ? bv : pv);
        idx = keep ? idx : (pk ? bi : pi);

        vmin = __shfl_sync(FULLMASK, val, 7);
        if (!m) break;
        m &= __ballot_sync(FULLMASK, v > vmin);   // prune with tighter vmin
    }
}

// Quad: one ballot per 4 elements; exact path only on a hit.
static __device__ __forceinline__ void quad(uint4 q, uint32_t ubase,
                                            float& val, uint32_t& idx,
                                            float& vmin, bool lane0) {
    const float vx = __uint_as_float(q.x);
    const float vy = __uint_as_float(q.y);
    const float vz = __uint_as_float(q.z);
    const float vw = __uint_as_float(q.w);
    const float qm = fmaxf(fmaxf(vx, vy), fmaxf(vz, vw));
    if (__ballot_sync(FULLMASK, qm > vmin)) {
        proc(vx, ubase + 0, val, idx, vmin, lane0);
        proc(vy, ubase + 1, val, idx, vmin, lane0);
        proc(vz, ubase + 2, val, idx, vmin, lane0);
        proc(vw, ubase + 3, val, idx, vmin, lane0);
    }
}

__global__ void __launch_bounds__(256) kmax8_kernel(const float* __restrict__ x,
                                                    float* __restrict__ out,
                                                    int nrows) {
    // per-warp double buffer: 128 uint4 = 2KB per stage, 8 warps x 2 stages
    __shared__ __align__(16) uint4 sbuf[8][2][128];

    const int w    = (int)(threadIdx.x >> 5);
    const int gw   = (int)((blockIdx.x * blockDim.x + threadIdx.x) >> 5);
    const int lane = threadIdx.x & 31;
    if (gw >= nrows) return;

    const uint4* row = reinterpret_cast<const uint4*>(x) + (size_t)gw * 1024;

    float    val  = __int_as_float(0xff800000);  // -inf (lanes 0..7 = top-8)
    uint32_t idx  = 0;
    float    vmin = __int_as_float(0xff800000);
    const bool lane0 = (lane == 0);

    // prefetch iteration 0 into stage 0
#pragma unroll
    for (int j = 0; j < 4; ++j)
        cpa16(&sbuf[w][0][j * 32 + lane], row + j * 32 + lane);
    CPA_COMMIT();

    // 8 iterations x 16 elements per lane, processed from smem.
#pragma unroll 1
    for (int it = 0; it < 8; ++it) {
        if (it < 7) {
            // prefetch next iteration into the other stage, then wait until
            // only that group is pending (=> current stage is complete)
            const uint4* np = row + (it + 1) * 128 + lane;
            uint4* nb = &sbuf[w][(it + 1) & 1][lane];
#pragma unroll
            for (int j = 0; j < 4; ++j)
                cpa16(nb + j * 32, np + j * 32);
            CPA_COMMIT();
            CPA_WAIT(1);
        } else {
            CPA_WAIT(0);
        }

        const uint4* b = sbuf[w][it & 1];
        const uint32_t u0 = (uint32_t)(it * 512);
        quad(b[lane],      u0 + 0,   val, idx, vmin, lane0);
        quad(b[32 + lane], u0 + 128, val, idx, vmin, lane0);
        quad(b[64 + lane], u0 + 256, val, idx, vmin, lane0);
        quad(b[96 + lane], u0 + 384, val, idx, vmin, lane0);
    }

    // Epilogue: lanes 0..7 hold the top-8 (val desc, unique idx).
    // rank = number of held indices smaller than mine -> output position.
    int rank = 0;
#pragma unroll
    for (int dd = 1; dd < 8; ++dd) {
        uint32_t oi = __shfl_sync(FULLMASK, idx, (lane + dd) & 7);
        rank += (oi < idx) ? 1 : 0;
    }
    if (lane < 8) out[(size_t)gw * 8 + rank] = val;
}

extern "C" void kernel_launch(void* const* d_in, const int* in_sizes, int n_in,
                              void* d_out, int out_size) {
    const float* x = (const float*)d_in[0];
    float* out = (float*)d_out;
    int nrows = in_sizes[0] / 4096;
    const int threads = 256;
    const int warps_per_block = threads / 32;
    int blocks = (nrows + warps_per_block - 1) / warps_per_block;
    kmax8_kernel<<<blocks, threads>>>(x, out, nrows);
}